// round 11
// baseline (speedup 1.0000x reference)
#include <cuda_runtime.h>
#include <cuda_bf16.h>
#include <cuda_fp16.h>
#include <stdint.h>
#include <math.h>

#define S_LEN 1024
#define BH_N  64
#define NCH   16
#define NT    256

// smem (bytes): Qhi 0-16K | Qlo 16K-32K | Qf16 32K-48K | K/V chunk bufs 48K-80K
#define SQH  0
#define SQL  16384
#define SQ16 32768
#define SKH  49152
#define SKL  57344
#define SVH  65536
#define SVL  73728
#define SMEM_BYTES (80*1024)

static __device__ __forceinline__ uint32_t cvta_s(const void* p){
    uint32_t a; asm("{ .reg .u64 t; cvta.to.shared.u64 t, %1; cvt.u32.u64 %0, t; }":"=r"(a):"l"(p)); return a;
}
static __device__ __forceinline__ uint32_t swz(uint32_t base,int row,int col8){
    return base + (row<<7) + (((col8 ^ (row&7)))<<4);
}
static __device__ __forceinline__ void ldsm4(uint32_t a,uint32_t r[4]){
    asm volatile("ldmatrix.sync.aligned.m8n8.x4.shared.b16 {%0,%1,%2,%3},[%4];"
        :"=r"(r[0]),"=r"(r[1]),"=r"(r[2]),"=r"(r[3]):"r"(a));
}
static __device__ __forceinline__ void ldsm4t(uint32_t a,uint32_t r[4]){
    asm volatile("ldmatrix.sync.aligned.m8n8.x4.trans.shared.b16 {%0,%1,%2,%3},[%4];"
        :"=r"(r[0]),"=r"(r[1]),"=r"(r[2]),"=r"(r[3]):"r"(a));
}
static __device__ __forceinline__ void mma16816(float* d,const uint32_t* a,uint32_t b0,uint32_t b1){
    asm volatile("mma.sync.aligned.m16n8k16.row.col.f32.bf16.bf16.f32 "
        "{%0,%1,%2,%3},{%4,%5,%6,%7},{%8,%9},{%0,%1,%2,%3};"
        :"+f"(d[0]),"+f"(d[1]),"+f"(d[2]),"+f"(d[3])
        :"r"(a[0]),"r"(a[1]),"r"(a[2]),"r"(a[3]),"r"(b0),"r"(b1));
}
static __device__ __forceinline__ void mma16816h(float* d,const uint32_t* a,uint32_t b0,uint32_t b1){
    asm volatile("mma.sync.aligned.m16n8k16.row.col.f32.f16.f16.f32 "
        "{%0,%1,%2,%3},{%4,%5,%6,%7},{%8,%9},{%0,%1,%2,%3};"
        :"+f"(d[0]),"+f"(d[1]),"+f"(d[2]),"+f"(d[3])
        :"r"(a[0]),"r"(a[1]),"r"(a[2]),"r"(a[3]),"r"(b0),"r"(b1));
}
static __device__ __forceinline__ uint32_t pk(__nv_bfloat16 a,__nv_bfloat16 b){
    __nv_bfloat162 v(a,b); return *reinterpret_cast<uint32_t*>(&v);
}
static __device__ __forceinline__ uint32_t pkh(float x,float y){
    __half2 v(__float2half(x),__float2half(y)); return *reinterpret_cast<uint32_t*>(&v);
}
static __device__ __forceinline__ void sts16(uint32_t a,const uint32_t r[4]){
    asm volatile("st.shared.v4.b32 [%0],{%1,%2,%3,%4};"
        ::"r"(a),"r"(r[0]),"r"(r[1]),"r"(r[2]),"r"(r[3]):"memory");
}
static __device__ __forceinline__ void ldg8(float* r,const float* g){
    float4 a=__ldg((const float4*)g), b=__ldg((const float4*)g+1);
    r[0]=a.x;r[1]=a.y;r[2]=a.z;r[3]=a.w;r[4]=b.x;r[5]=b.y;r[6]=b.z;r[7]=b.w;
}
// store 8 floats as fp16 16B chunk at swizzled slot c16
static __device__ __forceinline__ void sts_h16(uint32_t s,int c16,const float* f){
    uint32_t h[4];
    #pragma unroll
    for(int k=0;k<4;++k) h[k]=pkh(f[2*k],f[2*k+1]);
    uint32_t off=((uint32_t)c16)<<4; off^=(off>>3)&0x70;
    sts16(s+off,h);
}
// fill ROWS x 64 fp32 tile -> bf16 hi/lo split, swizzled smem
template<int ROWS>
static __device__ __forceinline__ void fill(const float* __restrict__ g, uint32_t shi, uint32_t slo, int t){
    #pragma unroll
    for(int i=0;i<ROWS/32;++i){
        int c16=t+i*256;
        float f[8]; ldg8(f,g+(size_t)c16*8);
        uint32_t h[4],l[4];
        #pragma unroll
        for(int k=0;k<4;++k){
            float x=f[2*k], y=f[2*k+1];
            __nv_bfloat16 hx=__float2bfloat16(x), hy=__float2bfloat16(y);
            __nv_bfloat16 lx=__float2bfloat16(x-__bfloat162float(hx));
            __nv_bfloat16 ly=__float2bfloat16(y-__bfloat162float(hy));
            h[k]=pk(hx,hy); l[k]=pk(lx,ly);
        }
        uint32_t off=((uint32_t)c16)<<4; off^=(off>>3)&0x70;
        sts16(shi+off,h); sts16(slo+off,l);
    }
}
// Q fill: bf16 hi/lo (persists) + fp16 copy (pass 1)
static __device__ __forceinline__ void fillQ(const float* __restrict__ g, uint32_t shi, uint32_t slo, uint32_t s16, int t){
    #pragma unroll
    for(int i=0;i<4;++i){
        int c16=t+i*256;
        float f[8]; ldg8(f,g+(size_t)c16*8);
        uint32_t h[4],l[4],x16[4];
        #pragma unroll
        for(int k=0;k<4;++k){
            float x=f[2*k], y=f[2*k+1];
            __nv_bfloat16 hx=__float2bfloat16(x), hy=__float2bfloat16(y);
            __nv_bfloat16 lx=__float2bfloat16(x-__bfloat162float(hx));
            __nv_bfloat16 ly=__float2bfloat16(y-__bfloat162float(hy));
            h[k]=pk(hx,hy); l[k]=pk(lx,ly); x16[k]=pkh(x,y);
        }
        uint32_t off=((uint32_t)c16)<<4; off^=(off>>3)&0x70;
        sts16(shi+off,h); sts16(slo+off,l); sts16(s16+off,x16);
    }
}

__global__ void __launch_bounds__(NT,2) attn_mma_kernel(
    const float* __restrict__ Q,const float* __restrict__ K,const float* __restrict__ V,
    const float* __restrict__ Bias,float* __restrict__ Out,float* __restrict__ Wout)
{
    extern __shared__ char smem[];
    const uint32_t sb=cvta_s(smem);
    const int t=threadIdx.x, w=t>>5, lane=t&31;
    const int qt=blockIdx.x, bh=blockIdx.y;
    const int qr=lane>>2, qc=(lane&3)*2;
    const int m0=qt*128;
    const int row_lo=m0+w*16+qr, row_hi=row_lo+8;

    const float* Kg=K+(size_t)bh*S_LEN*64;
    const float* Vg=V+(size_t)bh*S_LEN*64;

    // Q tile -> smem: bf16 split (persists) + fp16 (pass 1)
    fillQ(Q+((size_t)bh*S_LEN+m0)*64, sb+SQH, sb+SQL, sb+SQ16, t);

    const int arow=16*w+(lane&7)+8*((lane>>3)&1);
    const int acolb=lane>>4;
    const int brow7=lane&7, bcol=lane>>3;
    const float* bias_lo=Bias+(size_t)row_lo*S_LEN;
    const float* bias_hi=Bias+(size_t)row_hi*S_LEN;

    float sum_lo=0.f,sum_hi=0.f;
    __syncthreads();

    // ===== PASS 1: row sums, single-term fp16, K staged in regs (R9 structure) =====
    {
        uint32_t A1[4][4];
        #pragma unroll
        for(int ks=0;ks<4;++ks) ldsm4(swz(sb+SQ16,arow,2*ks+acolb),A1[ks]);
        float kr[16];
        ldg8(kr,   Kg+(size_t)t*8);
        ldg8(kr+8, Kg+(size_t)(t+256)*8);
        for(int c=0;c<NCH;++c){
            sts_h16(sb+SKH,t,kr);
            sts_h16(sb+SKH,t+256,kr+8);
            __syncthreads();
            if(c+1<NCH){
                ldg8(kr,   Kg+(size_t)(c+1)*4096+(size_t)t*8);
                ldg8(kr+8, Kg+(size_t)(c+1)*4096+(size_t)(t+256)*8);
            }
            #pragma unroll
            for(int j=0;j<8;++j){
                float Sj[4]={0.f,0.f,0.f,0.f};
                #pragma unroll
                for(int s2=0;s2<2;++s2){
                    uint32_t Bh[4];
                    ldsm4(swz(sb+SKH,8*j+brow7,4*s2+bcol),Bh);
                    #pragma unroll
                    for(int s=0;s<2;++s)
                        mma16816h(Sj,A1[2*s2+s],Bh[2*s],Bh[2*s+1]);
                }
                float2 blo=__ldg((const float2*)(bias_lo+c*64+8*j+qc));
                float2 bhi=__ldg((const float2*)(bias_hi+c*64+8*j+qc));
                sum_lo+=__expf(fmaf(Sj[0],0.125f,blo.x))+__expf(fmaf(Sj[1],0.125f,blo.y));
                sum_hi+=__expf(fmaf(Sj[2],0.125f,bhi.x))+__expf(fmaf(Sj[3],0.125f,bhi.y));
            }
            __syncthreads();
        }
    }
    sum_lo+=__shfl_xor_sync(~0u,sum_lo,1); sum_lo+=__shfl_xor_sync(~0u,sum_lo,2);
    sum_hi+=__shfl_xor_sync(~0u,sum_hi,1); sum_hi+=__shfl_xor_sync(~0u,sum_hi,2);
    const float inv_lo=1.f/sum_lo, inv_hi=1.f/sum_hi;

    float O[8][4];
    #pragma unroll
    for(int j=0;j<8;++j){O[j][0]=0.f;O[j][1]=0.f;O[j][2]=0.f;O[j][3]=0.f;}

    float* w_lo=Wout+((size_t)bh<<20)+(size_t)row_lo*S_LEN;
    float* w_hi=Wout+((size_t)bh<<20)+(size_t)row_hi*S_LEN;

    // =================== PASS 2: weights + PV (R9 verbatim) ===================
    for(int c=0;c<NCH;++c){
        __syncthreads();
        fill<64>(Kg+(size_t)c*4096, sb+SKH, sb+SKL, t);
        fill<64>(Vg+(size_t)c*4096, sb+SVH, sb+SVL, t);
        __syncthreads();
        uint32_t Ah[4][4],Al[4][4];
        #pragma unroll
        for(int ks=0;ks<4;++ks){
            ldsm4(swz(sb+SQH,arow,2*ks+acolb),Ah[ks]);
            ldsm4(swz(sb+SQL,arow,2*ks+acolb),Al[ks]);
        }
        uint32_t Ph[4][4],Pl[4][4];
        #pragma unroll
        for(int j=0;j<8;++j){
            float Sj[4]={0.f,0.f,0.f,0.f};
            #pragma unroll
            for(int s2=0;s2<2;++s2){
                uint32_t Bh[4],Bl[4];
                ldsm4(swz(sb+SKH,8*j+brow7,4*s2+bcol),Bh);
                ldsm4(swz(sb+SKL,8*j+brow7,4*s2+bcol),Bl);
                #pragma unroll
                for(int s=0;s<2;++s){
                    mma16816(Sj,Ah[2*s2+s],Bh[2*s],Bh[2*s+1]);
                    mma16816(Sj,Ah[2*s2+s],Bl[2*s],Bl[2*s+1]);
                    mma16816(Sj,Al[2*s2+s],Bh[2*s],Bh[2*s+1]);
                }
            }
            float2 blo=__ldg((const float2*)(bias_lo+c*64+8*j+qc));
            float2 bhi=__ldg((const float2*)(bias_hi+c*64+8*j+qc));
            float p0=__expf(fmaf(Sj[0],0.125f,blo.x))*inv_lo;
            float p1=__expf(fmaf(Sj[1],0.125f,blo.y))*inv_lo;
            float p2=__expf(fmaf(Sj[2],0.125f,bhi.x))*inv_hi;
            float p3=__expf(fmaf(Sj[3],0.125f,bhi.y))*inv_hi;
            asm volatile("st.global.cs.v2.f32 [%0],{%1,%2};"::"l"(w_lo+c*64+8*j+qc),"f"(p0),"f"(p1):"memory");
            asm volatile("st.global.cs.v2.f32 [%0],{%1,%2};"::"l"(w_hi+c*64+8*j+qc),"f"(p2),"f"(p3):"memory");
            __nv_bfloat16 h0=__float2bfloat16(p0),h1=__float2bfloat16(p1);
            __nv_bfloat16 h2=__float2bfloat16(p2),h3=__float2bfloat16(p3);
            int s=j>>1, b2=2*(j&1);
            Ph[s][b2]  =pk(h0,h1);
            Ph[s][b2+1]=pk(h2,h3);
            Pl[s][b2]  =pk(__float2bfloat16(p0-__bfloat162float(h0)),
                           __float2bfloat16(p1-__bfloat162float(h1)));
            Pl[s][b2+1]=pk(__float2bfloat16(p2-__bfloat162float(h2)),
                           __float2bfloat16(p3-__bfloat162float(h3)));
        }
        #pragma unroll
        for(int j=0;j<8;++j){
            #pragma unroll
            for(int s2=0;s2<2;++s2){
                uint32_t Bh[4],Bl[4];
                int vr=32*s2+lane;
                ldsm4t(swz(sb+SVH,vr,j),Bh);
                ldsm4t(swz(sb+SVL,vr,j),Bl);
                #pragma unroll
                for(int s=0;s<2;++s){
                    mma16816(O[j],Ph[2*s2+s],Bh[2*s],Bh[2*s+1]);
                    mma16816(O[j],Ph[2*s2+s],Bl[2*s],Bl[2*s+1]);
                    mma16816(O[j],Pl[2*s2+s],Bh[2*s],Bh[2*s+1]);
                }
            }
        }
    }
    float* o_lo=Out+((size_t)bh*S_LEN+row_lo)*64;
    float* o_hi=Out+((size_t)bh*S_LEN+row_hi)*64;
    #pragma unroll
    for(int j=0;j<8;++j){
        *(float2*)(o_lo+8*j+qc)=make_float2(O[j][0],O[j][1]);
        *(float2*)(o_hi+8*j+qc)=make_float2(O[j][2],O[j][3]);
    }
}

extern "C" void kernel_launch(void* const* d_in, const int* in_sizes, int n_in,
                              void* d_out, int out_size)
{
    const float* Q=(const float*)d_in[0];
    const float* K=(const float*)d_in[1];
    const float* V=(const float*)d_in[2];
    const float* Bias=(const float*)d_in[3];
    float* Out=(float*)d_out;
    float* Wout=Out+(size_t)BH_N*S_LEN*64;

    cudaFuncSetAttribute(attn_mma_kernel,
                         cudaFuncAttributeMaxDynamicSharedMemorySize, SMEM_BYTES);
    attn_mma_kernel<<<dim3(S_LEN/128,BH_N),NT,SMEM_BYTES>>>(Q,K,V,Bias,Out,Wout);
}

// round 14
// speedup vs baseline: 1.6717x; 1.6717x over previous
#include <cuda_runtime.h>
#include <cuda_bf16.h>
#include <stdint.h>
#include <math.h>

#define S_LEN 1024
#define BH_N  64
#define NCH   16
#define NT    256

// smem (bytes): Qhi 0-16K | Qlo 16K-32K (persist)
// pass-1: K-hi double buffers 32K-40K, 40K-48K
// pass-2: 32KB buffers (KH|KL|VH|VL 8K each) at 32K and 64K
#define SQH  0
#define SQL  16384
#define P1B0 32768
#define P1B1 40960
#define P2B0 32768
#define P2B1 65536
#define SMEM_BYTES (96*1024)

// pre-split bf16 hi/lo K and V (8MB each, __device__ globals: no allocation)
__device__ __align__(16) __nv_bfloat16 g_Khi[(size_t)BH_N*S_LEN*64];
__device__ __align__(16) __nv_bfloat16 g_Klo[(size_t)BH_N*S_LEN*64];
__device__ __align__(16) __nv_bfloat16 g_Vhi[(size_t)BH_N*S_LEN*64];
__device__ __align__(16) __nv_bfloat16 g_Vlo[(size_t)BH_N*S_LEN*64];

static __device__ __forceinline__ uint32_t cvta_s(const void* p){
    uint32_t a; asm("{ .reg .u64 t; cvta.to.shared.u64 t, %1; cvt.u32.u64 %0, t; }":"=r"(a):"l"(p)); return a;
}
static __device__ __forceinline__ uint32_t swz(uint32_t base,int row,int col8){
    return base + (row<<7) + (((col8 ^ (row&7)))<<4);
}
static __device__ __forceinline__ void ldsm4(uint32_t a,uint32_t r[4]){
    asm volatile("ldmatrix.sync.aligned.m8n8.x4.shared.b16 {%0,%1,%2,%3},[%4];"
        :"=r"(r[0]),"=r"(r[1]),"=r"(r[2]),"=r"(r[3]):"r"(a));
}
static __device__ __forceinline__ void ldsm4t(uint32_t a,uint32_t r[4]){
    asm volatile("ldmatrix.sync.aligned.m8n8.x4.trans.shared.b16 {%0,%1,%2,%3},[%4];"
        :"=r"(r[0]),"=r"(r[1]),"=r"(r[2]),"=r"(r[3]):"r"(a));
}
static __device__ __forceinline__ void mma16816(float* d,const uint32_t* a,uint32_t b0,uint32_t b1){
    asm volatile("mma.sync.aligned.m16n8k16.row.col.f32.bf16.bf16.f32 "
        "{%0,%1,%2,%3},{%4,%5,%6,%7},{%8,%9},{%0,%1,%2,%3};"
        :"+f"(d[0]),"+f"(d[1]),"+f"(d[2]),"+f"(d[3])
        :"r"(a[0]),"r"(a[1]),"r"(a[2]),"r"(a[3]),"r"(b0),"r"(b1));
}
static __device__ __forceinline__ uint32_t pk(__nv_bfloat16 a,__nv_bfloat16 b){
    __nv_bfloat162 v(a,b); return *reinterpret_cast<uint32_t*>(&v);
}
static __device__ __forceinline__ void sts16(uint32_t a,const uint32_t r[4]){
    asm volatile("st.shared.v4.b32 [%0],{%1,%2,%3,%4};"
        ::"r"(a),"r"(r[0]),"r"(r[1]),"r"(r[2]),"r"(r[3]):"memory");
}
static __device__ __forceinline__ void ldg8(float* r,const float* g){
    float4 a=__ldg((const float4*)g), b=__ldg((const float4*)g+1);
    r[0]=a.x;r[1]=a.y;r[2]=a.z;r[3]=a.w;r[4]=b.x;r[5]=b.y;r[6]=b.z;r[7]=b.w;
}
#define CP_COMMIT asm volatile("cp.async.commit_group;":::"memory")
#define CP_WAIT0  asm volatile("cp.async.wait_group 0;":::"memory")
#define CP_WAIT1  asm volatile("cp.async.wait_group 1;":::"memory")
static __device__ __forceinline__ void cpa16(uint32_t d,const void* s){
    asm volatile("cp.async.cg.shared.global [%0],[%1],16;"::"r"(d),"l"(s):"memory");
}
// 64x64 bf16 tile (8KB) gmem -> swizzled smem: 2 cp.async per thread
static __device__ __forceinline__ void cpfill(const __nv_bfloat16* __restrict__ g, uint32_t s, int t){
    #pragma unroll
    for(int i=0;i<2;++i){
        int c16=t+i*256;
        uint32_t off=((uint32_t)c16)<<4; off^=(off>>3)&0x70;
        cpa16(s+off, g+(size_t)c16*8);
    }
}
// Q fill (in-kernel, once): 128x64 fp32 -> bf16 hi/lo, swizzled
static __device__ __forceinline__ void fillQ(const float* __restrict__ g, uint32_t shi, uint32_t slo, int t){
    #pragma unroll
    for(int i=0;i<4;++i){
        int c16=t+i*256;
        float f[8]; ldg8(f,g+(size_t)c16*8);
        uint32_t h[4],l[4];
        #pragma unroll
        for(int k=0;k<4;++k){
            float x=f[2*k], y=f[2*k+1];
            __nv_bfloat16 hx=__float2bfloat16(x), hy=__float2bfloat16(y);
            __nv_bfloat16 lx=__float2bfloat16(x-__bfloat162float(hx));
            __nv_bfloat16 ly=__float2bfloat16(y-__bfloat162float(hy));
            h[k]=pk(hx,hy); l[k]=pk(lx,ly);
        }
        uint32_t off=((uint32_t)c16)<<4; off^=(off>>3)&0x70;
        sts16(shi+off,h); sts16(slo+off,l);
    }
}

// ---- precompute: split K,V -> bf16 hi/lo in global ----
__global__ void cvt_kernel(const float* __restrict__ K,const float* __restrict__ V){
    size_t i=((size_t)blockIdx.x*256+threadIdx.x)*4;
    const float* s = blockIdx.y? V:K;
    __nv_bfloat16* hi = blockIdx.y? g_Vhi:g_Khi;
    __nv_bfloat16* lo = blockIdx.y? g_Vlo:g_Klo;
    float4 f=*(const float4*)(s+i);
    __nv_bfloat16 h0=__float2bfloat16(f.x),h1=__float2bfloat16(f.y);
    __nv_bfloat16 h2=__float2bfloat16(f.z),h3=__float2bfloat16(f.w);
    *(uint2*)(hi+i)=make_uint2(pk(h0,h1),pk(h2,h3));
    *(uint2*)(lo+i)=make_uint2(
        pk(__float2bfloat16(f.x-__bfloat162float(h0)),__float2bfloat16(f.y-__bfloat162float(h1))),
        pk(__float2bfloat16(f.z-__bfloat162float(h2)),__float2bfloat16(f.w-__bfloat162float(h3))));
}

__global__ void __launch_bounds__(NT,2) attn_mma_kernel(
    const float* __restrict__ Q,const float* __restrict__ Bias,
    float* __restrict__ Out,float* __restrict__ Wout)
{
    extern __shared__ char smem[];
    const uint32_t sb=cvta_s(smem);
    const int t=threadIdx.x, w=t>>5, lane=t&31;
    const int qt=blockIdx.x, bh=blockIdx.y;
    const int qr=lane>>2, qc=(lane&3)*2;
    const int m0=qt*128;
    const int row_lo=m0+w*16+qr, row_hi=row_lo+8;
    const size_t base=(size_t)bh*S_LEN*64;

    // Q tile -> smem bf16 split, once (persists both passes)
    fillQ(Q+((size_t)bh*S_LEN+m0)*64, sb+SQH, sb+SQL, t);

    const int arow=16*w+(lane&7)+8*((lane>>3)&1);
    const int acolb=lane>>4;
    const int brow7=lane&7, bcol=lane>>3;
    const float* bias_lo=Bias+(size_t)row_lo*S_LEN;
    const float* bias_hi=Bias+(size_t)row_hi*S_LEN;

    float sum_lo=0.f,sum_hi=0.f;
    __syncthreads();

    // ===== PASS 1: row sums, 2-term bf16 (full-Q x K-hi), cp.async dbl-buffered =====
    {
        uint32_t A1h[4][4],A1l[4][4];
        #pragma unroll
        for(int ks=0;ks<4;++ks){
            ldsm4(swz(sb+SQH,arow,2*ks+acolb),A1h[ks]);
            ldsm4(swz(sb+SQL,arow,2*ks+acolb),A1l[ks]);
        }
        const __nv_bfloat16* Kh=g_Khi+base;
        cpfill(Kh, sb+P1B0, t); CP_COMMIT;
        for(int c=0;c<NCH;++c){
            const uint32_t kb = (c&1)? sb+P1B1 : sb+P1B0;
            if(c+1<NCH){
                cpfill(Kh+(size_t)(c+1)*4096, (c&1)? sb+P1B0 : sb+P1B1, t);
                CP_COMMIT; CP_WAIT1;
            } else CP_WAIT0;
            __syncthreads();
            #pragma unroll
            for(int j=0;j<8;++j){
                float Sj[4]={0.f,0.f,0.f,0.f};
                #pragma unroll
                for(int s2=0;s2<2;++s2){
                    uint32_t Bh[4];
                    ldsm4(swz(kb,8*j+brow7,4*s2+bcol),Bh);
                    #pragma unroll
                    for(int s=0;s<2;++s){
                        mma16816(Sj,A1h[2*s2+s],Bh[2*s],Bh[2*s+1]);
                        mma16816(Sj,A1l[2*s2+s],Bh[2*s],Bh[2*s+1]);
                    }
                }
                float2 blo=__ldg((const float2*)(bias_lo+c*64+8*j+qc));
                float2 bhi=__ldg((const float2*)(bias_hi+c*64+8*j+qc));
                sum_lo+=__expf(fmaf(Sj[0],0.125f,blo.x))+__expf(fmaf(Sj[1],0.125f,blo.y));
                sum_hi+=__expf(fmaf(Sj[2],0.125f,bhi.x))+__expf(fmaf(Sj[3],0.125f,bhi.y));
            }
            __syncthreads();
        }
    }
    sum_lo+=__shfl_xor_sync(~0u,sum_lo,1); sum_lo+=__shfl_xor_sync(~0u,sum_lo,2);
    sum_hi+=__shfl_xor_sync(~0u,sum_hi,1); sum_hi+=__shfl_xor_sync(~0u,sum_hi,2);
    const float inv_lo=1.f/sum_lo, inv_hi=1.f/sum_hi;

    float O[8][4];
    #pragma unroll
    for(int j=0;j<8;++j){O[j][0]=0.f;O[j][1]=0.f;O[j][2]=0.f;O[j][3]=0.f;}

    float* w_lo=Wout+((size_t)bh<<20)+(size_t)row_lo*S_LEN;
    float* w_hi=Wout+((size_t)bh<<20)+(size_t)row_hi*S_LEN;

    // ===== PASS 2: weights + PV, 3-term bf16 (R9 math), cp.async dbl-buffered =====
    const __nv_bfloat16 *Khg=g_Khi+base,*Klg=g_Klo+base,*Vhg=g_Vhi+base,*Vlg=g_Vlo+base;
    cpfill(Khg,sb+P2B0,t); cpfill(Klg,sb+P2B0+8192,t);
    cpfill(Vhg,sb+P2B0+16384,t); cpfill(Vlg,sb+P2B0+24576,t);
    CP_COMMIT;
    for(int c=0;c<NCH;++c){
        const uint32_t bc = (c&1)? sb+P2B1 : sb+P2B0;
        if(c+1<NCH){
            const uint32_t bn = (c&1)? sb+P2B0 : sb+P2B1;
            size_t o=(size_t)(c+1)*4096;
            cpfill(Khg+o,bn,t); cpfill(Klg+o,bn+8192,t);
            cpfill(Vhg+o,bn+16384,t); cpfill(Vlg+o,bn+24576,t);
            CP_COMMIT; CP_WAIT1;
        } else CP_WAIT0;
        __syncthreads();
        uint32_t Ah[4][4],Al[4][4];
        #pragma unroll
        for(int ks=0;ks<4;++ks){
            ldsm4(swz(sb+SQH,arow,2*ks+acolb),Ah[ks]);
            ldsm4(swz(sb+SQL,arow,2*ks+acolb),Al[ks]);
        }
        uint32_t Ph[4][4],Pl[4][4];
        #pragma unroll
        for(int j=0;j<8;++j){
            float Sj[4]={0.f,0.f,0.f,0.f};
            #pragma unroll
            for(int s2=0;s2<2;++s2){
                uint32_t Bh[4],Bl[4];
                ldsm4(swz(bc,8*j+brow7,4*s2+bcol),Bh);
                ldsm4(swz(bc+8192,8*j+brow7,4*s2+bcol),Bl);
                #pragma unroll
                for(int s=0;s<2;++s){
                    mma16816(Sj,Ah[2*s2+s],Bh[2*s],Bh[2*s+1]);
                    mma16816(Sj,Ah[2*s2+s],Bl[2*s],Bl[2*s+1]);
                    mma16816(Sj,Al[2*s2+s],Bh[2*s],Bh[2*s+1]);
                }
            }
            float2 blo=__ldg((const float2*)(bias_lo+c*64+8*j+qc));
            float2 bhi=__ldg((const float2*)(bias_hi+c*64+8*j+qc));
            float p0=__expf(fmaf(Sj[0],0.125f,blo.x))*inv_lo;
            float p1=__expf(fmaf(Sj[1],0.125f,blo.y))*inv_lo;
            float p2=__expf(fmaf(Sj[2],0.125f,bhi.x))*inv_hi;
            float p3=__expf(fmaf(Sj[3],0.125f,bhi.y))*inv_hi;
            asm volatile("st.global.cs.v2.f32 [%0],{%1,%2};"::"l"(w_lo+c*64+8*j+qc),"f"(p0),"f"(p1):"memory");
            asm volatile("st.global.cs.v2.f32 [%0],{%1,%2};"::"l"(w_hi+c*64+8*j+qc),"f"(p2),"f"(p3):"memory");
            __nv_bfloat16 h0=__float2bfloat16(p0),h1=__float2bfloat16(p1);
            __nv_bfloat16 h2=__float2bfloat16(p2),h3=__float2bfloat16(p3);
            int s=j>>1, b2=2*(j&1);
            Ph[s][b2]  =pk(h0,h1);
            Ph[s][b2+1]=pk(h2,h3);
            Pl[s][b2]  =pk(__float2bfloat16(p0-__bfloat162float(h0)),
                           __float2bfloat16(p1-__bfloat162float(h1)));
            Pl[s][b2+1]=pk(__float2bfloat16(p2-__bfloat162float(h2)),
                           __float2bfloat16(p3-__bfloat162float(h3)));
        }
        #pragma unroll
        for(int j=0;j<8;++j){
            #pragma unroll
            for(int s2=0;s2<2;++s2){
                uint32_t Bh[4],Bl[4];
                int vr=32*s2+lane;
                ldsm4t(swz(bc+16384,vr,j),Bh);
                ldsm4t(swz(bc+24576,vr,j),Bl);
                #pragma unroll
                for(int s=0;s<2;++s){
                    mma16816(O[j],Ph[2*s2+s],Bh[2*s],Bh[2*s+1]);
                    mma16816(O[j],Ph[2*s2+s],Bl[2*s],Bl[2*s+1]);
                    mma16816(O[j],Pl[2*s2+s],Bh[2*s],Bh[2*s+1]);
                }
            }
        }
        __syncthreads();   // all reads of bc done before next chunk's cp.async overwrites
    }
    float* o_lo=Out+((size_t)bh*S_LEN+row_lo)*64;
    float* o_hi=Out+((size_t)bh*S_LEN+row_hi)*64;
    #pragma unroll
    for(int j=0;j<8;++j){
        *(float2*)(o_lo+8*j+qc)=make_float2(O[j][0],O[j][1]);
        *(float2*)(o_hi+8*j+qc)=make_float2(O[j][2],O[j][3]);
    }
}

extern "C" void kernel_launch(void* const* d_in, const int* in_sizes, int n_in,
                              void* d_out, int out_size)
{
    const float* Q=(const float*)d_in[0];
    const float* K=(const float*)d_in[1];
    const float* V=(const float*)d_in[2];
    const float* Bias=(const float*)d_in[3];
    float* Out=(float*)d_out;
    float* Wout=Out+(size_t)BH_N*S_LEN*64;

    cvt_kernel<<<dim3(4096,2),256>>>(K,V);
    cudaFuncSetAttribute(attn_mma_kernel,
                         cudaFuncAttributeMaxDynamicSharedMemorySize, SMEM_BYTES);
    attn_mma_kernel<<<dim3(S_LEN/128,BH_N),NT,SMEM_BYTES>>>(Q,Bias,Out,Wout);
}

// round 15
// speedup vs baseline: 1.7032x; 1.0189x over previous
#include <cuda_runtime.h>
#include <cuda_bf16.h>
#include <stdint.h>
#include <math.h>

#define S_LEN 1024
#define BH_N  64
#define NCH   16
#define NT    256

// smem (bytes): Qhi 0-16K | Qlo 16K-32K (persist)
// chunk buffers (KH|KL|VH|VL 8K each): 32K and 64K ; inv[128] at 96K
#define SQH  0
#define SQL  16384
#define B0   32768
#define B1   65536
#define SINV 98304
#define SMEM_BYTES (98304+512)

// pre-split bf16 hi/lo K and V (8MB each, __device__ globals: no allocation)
__device__ __align__(16) __nv_bfloat16 g_Khi[(size_t)BH_N*S_LEN*64];
__device__ __align__(16) __nv_bfloat16 g_Klo[(size_t)BH_N*S_LEN*64];
__device__ __align__(16) __nv_bfloat16 g_Vhi[(size_t)BH_N*S_LEN*64];
__device__ __align__(16) __nv_bfloat16 g_Vlo[(size_t)BH_N*S_LEN*64];

static __device__ __forceinline__ uint32_t cvta_s(const void* p){
    uint32_t a; asm("{ .reg .u64 t; cvta.to.shared.u64 t, %1; cvt.u32.u64 %0, t; }":"=r"(a):"l"(p)); return a;
}
static __device__ __forceinline__ uint32_t swz(uint32_t base,int row,int col8){
    return base + (row<<7) + (((col8 ^ (row&7)))<<4);
}
static __device__ __forceinline__ void ldsm4(uint32_t a,uint32_t r[4]){
    asm volatile("ldmatrix.sync.aligned.m8n8.x4.shared.b16 {%0,%1,%2,%3},[%4];"
        :"=r"(r[0]),"=r"(r[1]),"=r"(r[2]),"=r"(r[3]):"r"(a));
}
static __device__ __forceinline__ void ldsm4t(uint32_t a,uint32_t r[4]){
    asm volatile("ldmatrix.sync.aligned.m8n8.x4.trans.shared.b16 {%0,%1,%2,%3},[%4];"
        :"=r"(r[0]),"=r"(r[1]),"=r"(r[2]),"=r"(r[3]):"r"(a));
}
static __device__ __forceinline__ void mma16816(float* d,const uint32_t* a,uint32_t b0,uint32_t b1){
    asm volatile("mma.sync.aligned.m16n8k16.row.col.f32.bf16.bf16.f32 "
        "{%0,%1,%2,%3},{%4,%5,%6,%7},{%8,%9},{%0,%1,%2,%3};"
        :"+f"(d[0]),"+f"(d[1]),"+f"(d[2]),"+f"(d[3])
        :"r"(a[0]),"r"(a[1]),"r"(a[2]),"r"(a[3]),"r"(b0),"r"(b1));
}
static __device__ __forceinline__ uint32_t pk(__nv_bfloat16 a,__nv_bfloat16 b){
    __nv_bfloat162 v(a,b); return *reinterpret_cast<uint32_t*>(&v);
}
static __device__ __forceinline__ void sts16(uint32_t a,const uint32_t r[4]){
    asm volatile("st.shared.v4.b32 [%0],{%1,%2,%3,%4};"
        ::"r"(a),"r"(r[0]),"r"(r[1]),"r"(r[2]),"r"(r[3]):"memory");
}
static __device__ __forceinline__ void ldg8(float* r,const float* g){
    float4 a=__ldg((const float4*)g), b=__ldg((const float4*)g+1);
    r[0]=a.x;r[1]=a.y;r[2]=a.z;r[3]=a.w;r[4]=b.x;r[5]=b.y;r[6]=b.z;r[7]=b.w;
}
#define CP_COMMIT asm volatile("cp.async.commit_group;":::"memory")
#define CP_WAIT0  asm volatile("cp.async.wait_group 0;":::"memory")
#define CP_WAIT1  asm volatile("cp.async.wait_group 1;":::"memory")
static __device__ __forceinline__ void cpa16(uint32_t d,const void* s){
    asm volatile("cp.async.cg.shared.global [%0],[%1],16;"::"r"(d),"l"(s):"memory");
}
// 64x64 bf16 tile (8KB) gmem -> swizzled smem: 2 cp.async per thread
static __device__ __forceinline__ void cpfill(const __nv_bfloat16* __restrict__ g, uint32_t s, int t){
    #pragma unroll
    for(int i=0;i<2;++i){
        int c16=t+i*256;
        uint32_t off=((uint32_t)c16)<<4; off^=(off>>3)&0x70;
        cpa16(s+off, g+(size_t)c16*8);
    }
}
// Q fill (in-kernel, once): 128x64 fp32 -> bf16 hi/lo, swizzled
static __device__ __forceinline__ void fillQ(const float* __restrict__ g, uint32_t shi, uint32_t slo, int t){
    #pragma unroll
    for(int i=0;i<4;++i){
        int c16=t+i*256;
        float f[8]; ldg8(f,g+(size_t)c16*8);
        uint32_t h[4],l[4];
        #pragma unroll
        for(int k=0;k<4;++k){
            float x=f[2*k], y=f[2*k+1];
            __nv_bfloat16 hx=__float2bfloat16(x), hy=__float2bfloat16(y);
            __nv_bfloat16 lx=__float2bfloat16(x-__bfloat162float(hx));
            __nv_bfloat16 ly=__float2bfloat16(y-__bfloat162float(hy));
            h[k]=pk(hx,hy); l[k]=pk(lx,ly);
        }
        uint32_t off=((uint32_t)c16)<<4; off^=(off>>3)&0x70;
        sts16(shi+off,h); sts16(slo+off,l);
    }
}

// ---- precompute: split K,V -> bf16 hi/lo in global ----
__global__ void cvt_kernel(const float* __restrict__ K,const float* __restrict__ V){
    size_t i=((size_t)blockIdx.x*256+threadIdx.x)*4;
    const float* s = blockIdx.y? V:K;
    __nv_bfloat16* hi = blockIdx.y? g_Vhi:g_Khi;
    __nv_bfloat16* lo = blockIdx.y? g_Vlo:g_Klo;
    float4 f=*(const float4*)(s+i);
    __nv_bfloat16 h0=__float2bfloat16(f.x),h1=__float2bfloat16(f.y);
    __nv_bfloat16 h2=__float2bfloat16(f.z),h3=__float2bfloat16(f.w);
    *(uint2*)(hi+i)=make_uint2(pk(h0,h1),pk(h2,h3));
    *(uint2*)(lo+i)=make_uint2(
        pk(__float2bfloat16(f.x-__bfloat162float(h0)),__float2bfloat16(f.y-__bfloat162float(h1))),
        pk(__float2bfloat16(f.z-__bfloat162float(h2)),__float2bfloat16(f.w-__bfloat162float(h3))));
}

__global__ void __launch_bounds__(NT,2) attn_mma_kernel(
    const float* __restrict__ Q,const float* __restrict__ Bias,
    float* __restrict__ Out,float* __restrict__ Wout)
{
    extern __shared__ char smem[];
    const uint32_t sb=cvta_s(smem);
    float* sm_inv=(float*)(smem+SINV);
    const int t=threadIdx.x, w=t>>5, lane=t&31;
    const int qt=blockIdx.x, bh=blockIdx.y;
    const int qr=lane>>2, qc=(lane&3)*2;
    const int m0=qt*128;
    const int row_lo=m0+w*16+qr, row_hi=row_lo+8;
    const size_t base=(size_t)bh*S_LEN*64;

    // Q tile -> smem bf16 split, once
    fillQ(Q+((size_t)bh*S_LEN+m0)*64, sb+SQH, sb+SQL, t);

    const int arow=16*w+(lane&7)+8*((lane>>3)&1);
    const int acolb=lane>>4;
    const int brow7=lane&7, bcol=lane>>3;
    const float* bias_lo=Bias+(size_t)row_lo*S_LEN;
    const float* bias_hi=Bias+(size_t)row_hi*S_LEN;

    float sum_lo=0.f,sum_hi=0.f;
    float O[8][4];
    #pragma unroll
    for(int j=0;j<8;++j){O[j][0]=0.f;O[j][1]=0.f;O[j][2]=0.f;O[j][3]=0.f;}

    float* w_lo=Wout+((size_t)bh<<20)+(size_t)row_lo*S_LEN;
    float* w_hi=Wout+((size_t)bh<<20)+(size_t)row_hi*S_LEN;

    __syncthreads();

    // ===== SINGLE PASS: unnormalized e, row sums, PV accumulate =====
    const __nv_bfloat16 *Khg=g_Khi+base,*Klg=g_Klo+base,*Vhg=g_Vhi+base,*Vlg=g_Vlo+base;
    cpfill(Khg,sb+B0,t); cpfill(Klg,sb+B0+8192,t);
    cpfill(Vhg,sb+B0+16384,t); cpfill(Vlg,sb+B0+24576,t);
    CP_COMMIT;
    for(int c=0;c<NCH;++c){
        const uint32_t bc = (c&1)? sb+B1 : sb+B0;
        if(c+1<NCH){
            const uint32_t bn = (c&1)? sb+B0 : sb+B1;
            size_t o=(size_t)(c+1)*4096;
            cpfill(Khg+o,bn,t); cpfill(Klg+o,bn+8192,t);
            cpfill(Vhg+o,bn+16384,t); cpfill(Vlg+o,bn+24576,t);
            CP_COMMIT; CP_WAIT1;
        } else CP_WAIT0;
        __syncthreads();
        uint32_t Ah[4][4],Al[4][4];
        #pragma unroll
        for(int ks=0;ks<4;++ks){
            ldsm4(swz(sb+SQH,arow,2*ks+acolb),Ah[ks]);
            ldsm4(swz(sb+SQL,arow,2*ks+acolb),Al[ks]);
        }
        uint32_t Ph[4][4],Pl[4][4];
        #pragma unroll
        for(int j=0;j<8;++j){
            float Sj[4]={0.f,0.f,0.f,0.f};
            #pragma unroll
            for(int s2=0;s2<2;++s2){
                uint32_t Bh[4],Bl[4];
                ldsm4(swz(bc,8*j+brow7,4*s2+bcol),Bh);
                ldsm4(swz(bc+8192,8*j+brow7,4*s2+bcol),Bl);
                #pragma unroll
                for(int s=0;s<2;++s){
                    mma16816(Sj,Ah[2*s2+s],Bh[2*s],Bh[2*s+1]);
                    mma16816(Sj,Ah[2*s2+s],Bl[2*s],Bl[2*s+1]);
                    mma16816(Sj,Al[2*s2+s],Bh[2*s],Bh[2*s+1]);
                }
            }
            float2 blo=__ldg((const float2*)(bias_lo+c*64+8*j+qc));
            float2 bhi=__ldg((const float2*)(bias_hi+c*64+8*j+qc));
            float e0=__expf(fmaf(Sj[0],0.125f,blo.x));
            float e1=__expf(fmaf(Sj[1],0.125f,blo.y));
            float e2=__expf(fmaf(Sj[2],0.125f,bhi.x));
            float e3=__expf(fmaf(Sj[3],0.125f,bhi.y));
            sum_lo+=e0+e1; sum_hi+=e2+e3;
            // plain stores: keep lines in L2 for the rescale re-read
            asm volatile("st.global.v2.f32 [%0],{%1,%2};"::"l"(w_lo+c*64+8*j+qc),"f"(e0),"f"(e1):"memory");
            asm volatile("st.global.v2.f32 [%0],{%1,%2};"::"l"(w_hi+c*64+8*j+qc),"f"(e2),"f"(e3):"memory");
            __nv_bfloat16 h0=__float2bfloat16(e0),h1=__float2bfloat16(e1);
            __nv_bfloat16 h2=__float2bfloat16(e2),h3=__float2bfloat16(e3);
            int s=j>>1, b2=2*(j&1);
            Ph[s][b2]  =pk(h0,h1);
            Ph[s][b2+1]=pk(h2,h3);
            Pl[s][b2]  =pk(__float2bfloat16(e0-__bfloat162float(h0)),
                           __float2bfloat16(e1-__bfloat162float(h1)));
            Pl[s][b2+1]=pk(__float2bfloat16(e2-__bfloat162float(h2)),
                           __float2bfloat16(e3-__bfloat162float(h3)));
        }
        #pragma unroll
        for(int j=0;j<8;++j){
            #pragma unroll
            for(int s2=0;s2<2;++s2){
                uint32_t Bh[4],Bl[4];
                int vr=32*s2+lane;
                ldsm4t(swz(bc+16384,vr,j),Bh);
                ldsm4t(swz(bc+24576,vr,j),Bl);
                #pragma unroll
                for(int s=0;s<2;++s){
                    mma16816(O[j],Ph[2*s2+s],Bh[2*s],Bh[2*s+1]);
                    mma16816(O[j],Ph[2*s2+s],Bl[2*s],Bl[2*s+1]);
                    mma16816(O[j],Pl[2*s2+s],Bh[2*s],Bh[2*s+1]);
                }
            }
        }
        __syncthreads();
    }

    // ===== epilogue: normalize O, publish inv, rescale weights block =====
    sum_lo+=__shfl_xor_sync(~0u,sum_lo,1); sum_lo+=__shfl_xor_sync(~0u,sum_lo,2);
    sum_hi+=__shfl_xor_sync(~0u,sum_hi,1); sum_hi+=__shfl_xor_sync(~0u,sum_hi,2);
    const float inv_lo=1.f/sum_lo, inv_hi=1.f/sum_hi;

    float* o_lo=Out+((size_t)bh*S_LEN+row_lo)*64;
    float* o_hi=Out+((size_t)bh*S_LEN+row_hi)*64;
    #pragma unroll
    for(int j=0;j<8;++j){
        *(float2*)(o_lo+8*j+qc)=make_float2(O[j][0]*inv_lo,O[j][1]*inv_lo);
        *(float2*)(o_hi+8*j+qc)=make_float2(O[j][2]*inv_hi,O[j][3]*inv_hi);
    }
    if((lane&3)==0){
        sm_inv[w*16+qr]   =inv_lo;
        sm_inv[w*16+qr+8] =inv_hi;
    }
    __syncthreads();   // orders e-stores (global) + inv (shared) within CTA

    // cooperative, coalesced rescale of this CTA's 128x1024 weight block
    float4* W4=(float4*)(Wout+((size_t)bh<<20)+(size_t)m0*S_LEN);
    for(int i=0;i<128;++i){
        float inv=sm_inv[i];
        int idx=t+i*256;
        float4 v=W4[idx];
        v.x*=inv; v.y*=inv; v.z*=inv; v.w*=inv;
        asm volatile("st.global.cs.v4.f32 [%0],{%1,%2,%3,%4};"
            ::"l"(W4+idx),"f"(v.x),"f"(v.y),"f"(v.z),"f"(v.w):"memory");
    }
}

extern "C" void kernel_launch(void* const* d_in, const int* in_sizes, int n_in,
                              void* d_out, int out_size)
{
    const float* Q=(const float*)d_in[0];
    const float* K=(const float*)d_in[1];
    const float* V=(const float*)d_in[2];
    const float* Bias=(const float*)d_in[3];
    float* Out=(float*)d_out;
    float* Wout=Out+(size_t)BH_N*S_LEN*64;

    cvt_kernel<<<dim3(4096,2),256>>>(K,V);
    cudaFuncSetAttribute(attn_mma_kernel,
                         cudaFuncAttributeMaxDynamicSharedMemorySize, SMEM_BYTES);
    attn_mma_kernel<<<dim3(S_LEN/128,BH_N),NT,SMEM_BYTES>>>(Q,Bias,Out,Wout);
}